// round 15
// baseline (speedup 1.0000x reference)
#include <cuda_runtime.h>
#include <cuda_bf16.h>

typedef unsigned int u32;
typedef unsigned long long u64;

#define Bb 64
#define Tt 512
#define Dd 1024
#define Hh 1024
#define Gblk 128

// ---------------- global scratch (allocation-free rule) ----------------
__device__ float g_Gx[(size_t)Tt * Bb * 2048];   // [t][b][n]
__device__ float g_Cx[(size_t)Tt * Bb * 1024];   // [t][b][n]
__device__ float g_h [Bb * Hh];                  // [b][c] fp32
__device__ float g_u [Bb * Hh];                  // [b][c] update gate
__device__ __nv_bfloat16 g_hhi [Bb * Hh];        // h split (written in B-tail)
__device__ __nv_bfloat16 g_hlo [Bb * Hh];
__device__ __nv_bfloat16 g_rhhi[Bb * Hh];        // r*h split (written in A-tail)
__device__ __nv_bfloat16 g_rhlo[Bb * Hh];
__device__ __nv_bfloat16 g_xhi[(size_t)Bb * Tt * Dd];
__device__ __nv_bfloat16 g_xlo[(size_t)Bb * Tt * Dd];
__device__ __nv_bfloat16 g_Whi[2048 * 2048];
__device__ __nv_bfloat16 g_Wlo[2048 * 2048];
__device__ __nv_bfloat16 g_Uhi[2048 * 1024];
__device__ __nv_bfloat16 g_Ulo[2048 * 1024];
__device__ unsigned g_arrive;                    // monotonic barrier counter

// ---------------- helpers ----------------
__device__ __forceinline__ unsigned ld_acq(const unsigned* p) {
    unsigned v; asm volatile("ld.global.acquire.gpu.u32 %0, [%1];" : "=r"(v) : "l"(p)); return v;
}
__device__ __forceinline__ void red_release(unsigned* p) {
    asm volatile("red.release.gpu.global.add.u32 [%0], 1;" :: "l"(p) : "memory");
}
__device__ __forceinline__ float sigf(float x) { return __fdividef(1.0f, 1.0f + __expf(-x)); }
__device__ __forceinline__ float tanh_fast(float x) {
    float e = __expf(-2.0f * x);
    return __fdividef(1.0f - e, 1.0f + e);
}
__device__ __forceinline__ u32 smem_u32(const void* p) {
    u32 a; asm("{ .reg .u64 t; cvta.to.shared.u64 t, %1; cvt.u32.u64 %0, t; }" : "=r"(a) : "l"(p));
    return a;
}
__device__ __forceinline__ u32 pk(__nv_bfloat16 a, __nv_bfloat16 b) {
    __nv_bfloat162 t; t.x = a; t.y = b; return *reinterpret_cast<u32*>(&t);
}
__device__ __forceinline__ __nv_bfloat16 bfh(float x) { return __float2bfloat16_rn(x); }
__device__ __forceinline__ __nv_bfloat16 bfl(float x, __nv_bfloat16 h) {
    return __float2bfloat16_rn(x - __bfloat162float(h));
}
__device__ __forceinline__ void prefetch_l2(const void* p) {
    asm volatile("prefetch.global.L2 [%0];" :: "l"(p));
}

// ---------------- tensor-core primitives (baseline PTX, sm_80+) ----------------
__device__ __forceinline__ void ldm4(u32* r, u32 a) {
    asm volatile("ldmatrix.sync.aligned.m8n8.x4.shared.b16 {%0,%1,%2,%3}, [%4];"
        : "=r"(r[0]), "=r"(r[1]), "=r"(r[2]), "=r"(r[3]) : "r"(a));
}
__device__ __forceinline__ void ldm4t(u32* r, u32 a) {
    asm volatile("ldmatrix.sync.aligned.m8n8.x4.trans.shared.b16 {%0,%1,%2,%3}, [%4];"
        : "=r"(r[0]), "=r"(r[1]), "=r"(r[2]), "=r"(r[3]) : "r"(a));
}
__device__ __forceinline__ void ldm2t(u32& r0, u32& r1, u32 a) {
    asm volatile("ldmatrix.sync.aligned.m8n8.x2.trans.shared.b16 {%0,%1}, [%2];"
        : "=r"(r0), "=r"(r1) : "r"(a));
}
__device__ __forceinline__ void mmaA(float* d, const u32* a, u32 b0, u32 b1) {
    asm volatile("mma.sync.aligned.m16n8k16.row.col.f32.bf16.bf16.f32 "
        "{%0,%1,%2,%3}, {%4,%5,%6,%7}, {%8,%9}, {%0,%1,%2,%3};"
        : "+f"(d[0]), "+f"(d[1]), "+f"(d[2]), "+f"(d[3])
        : "r"(a[0]), "r"(a[1]), "r"(a[2]), "r"(a[3]), "r"(b0), "r"(b1));
}
#define CPA16(dst, src) \
    asm volatile("cp.async.cg.shared.global [%0], [%1], 16;" :: "r"(dst), "l"(src))
#define CPA_COMMIT() asm volatile("cp.async.commit_group;")
#define CPA_WAIT1()  asm volatile("cp.async.wait_group 1;")
#define CPA_WAIT0()  asm volatile("cp.async.wait_group 0;")

// Full m16n32 k16 helper for the precompute kernel (unchanged from R13).
__device__ __forceinline__ void mma_k16(float (&acc)[4][4], u32 aaddr, u32 alo_d,
                                        u32 baddr, u32 blo_d) {
    u32 ah[4], al[4];
    ldm4(ah, aaddr);
    ldm4(al, aaddr + alo_d);
#pragma unroll
    for (int p = 0; p < 2; p++) {
        u32 bh[4], bl[4];
        ldm4t(bh, baddr + p * 32);
        ldm4t(bl, baddr + p * 32 + blo_d);
        mmaA(acc[2 * p],     ah, bh[0], bh[1]);
        mmaA(acc[2 * p],     al, bh[0], bh[1]);
        mmaA(acc[2 * p],     ah, bl[0], bl[1]);
        mmaA(acc[2 * p + 1], ah, bh[2], bh[3]);
        mmaA(acc[2 * p + 1], al, bh[2], bh[3]);
        mmaA(acc[2 * p + 1], ah, bl[2], bl[3]);
    }
}

// ---------------- conversion kernels ----------------
__global__ void __launch_bounds__(256) conv_split(
    const float4* __restrict__ src, int which, int n4)
{
    int i = blockIdx.x * blockDim.x + threadIdx.x;
    if (i >= n4) return;
    u32* hi; u32* lo;
    if (which == 0)      { hi = (u32*)g_xhi; lo = (u32*)g_xlo; }
    else if (which == 1) { hi = (u32*)g_Whi; lo = (u32*)g_Wlo; }
    else                 { hi = (u32*)g_Uhi; lo = (u32*)g_Ulo; }
    float4 v = src[i];
    __nv_bfloat16 hx = bfh(v.x), hy = bfh(v.y), hz = bfh(v.z), hw = bfh(v.w);
    hi[2 * i]     = pk(hx, hy);
    hi[2 * i + 1] = pk(hz, hw);
    lo[2 * i]     = pk(bfl(v.x, hx), bfl(v.y, hy));
    lo[2 * i + 1] = pk(bfl(v.z, hz), bfl(v.w, hw));
}

__global__ void __launch_bounds__(256) copy_h0(const float* __restrict__ h0)
{
    int i = (blockIdx.x * blockDim.x + threadIdx.x) * 2;
    if (i >= Bb * Hh) return;
    float2 v = *reinterpret_cast<const float2*>(&h0[i]);
    *reinterpret_cast<float2*>(&g_h[i]) = v;
    __nv_bfloat16 h0b = bfh(v.x), h1b = bfh(v.y);
    *reinterpret_cast<u32*>(&g_hhi[i]) = pk(h0b, h1b);
    *reinterpret_cast<u32*>(&g_hlo[i]) = pk(bfl(v.x, h0b), bfl(v.y, h1b));
}

// ---------------- precompute (x-path), t-batched (R13, unchanged) ----------------
#define PRE_SMEM 73728

__global__ void __launch_bounds__(256) gemm_pre_tc(
    const float* __restrict__ Wb, const float* __restrict__ Ub)
{
    extern __shared__ char smp[];
    const u32 sb32 = smem_u32(smp);
    const int tid = threadIdx.x;
    const int cb = blockIdx.x, tg = blockIdx.y;
    const bool isW = cb < 32;
    const __nv_bfloat16* whi = isW ? g_Whi : g_Uhi;
    const __nv_bfloat16* wlo = isW ? g_Wlo : g_Ulo;
    const float* bia = isW ? Wb : Ub;
    float* outg = isW ? g_Gx : g_Cx;
    const int ldn = isW ? 2048 : 1024;
    const int n0  = (isW ? cb : cb - 32) * 64;

    const int lane = tid & 31, w = tid >> 5;
    const int mt = (w & 3) * 16, nh = (w >> 2) * 32;
    const int row = lane & 15, lh = lane >> 4;

    float acc[4][4][4];
#pragma unroll
    for (int tt = 0; tt < 4; tt++)
#pragma unroll
        for (int i = 0; i < 4; i++)
#pragma unroll
            for (int j = 0; j < 4; j++) acc[tt][i][j] = 0.0f;

    auto copyW = [&](int ch) {
        const int k0 = ch * 64;
        const u32 wbuf = sb32 + (ch & 1) * 18432;
#pragma unroll
        for (int j = 0; j < 4; j++) {
            int idx = j * 256 + tid;
            int r = (idx >> 3) & 63, c8 = idx & 7;
            bool isLo = idx >= 512;
            const __nv_bfloat16* src = (isLo ? wlo : whi) + (size_t)(k0 + r) * ldn + n0 + c8 * 8;
            CPA16(wbuf + (isLo ? 9216 : 0) + r * 144 + c8 * 16, src);
        }
    };
    auto copyX = [&](int s) {
        const int ch = s >> 2, t = tg * 4 + (s & 3);
        const int k0 = ch * 64;
        const u32 xbuf = sb32 + 36864 + (s & 1) * 18432;
#pragma unroll
        for (int j = 0; j < 4; j++) {
            int idx = j * 256 + tid;
            int r = (idx >> 3) & 63, c8 = idx & 7;
            bool isLo = idx >= 512;
            const __nv_bfloat16* src = (isLo ? g_xlo : g_xhi) + ((size_t)r * Tt + t) * Dd + k0 + c8 * 8;
            CPA16(xbuf + (isLo ? 9216 : 0) + r * 144 + c8 * 16, src);
        }
    };

    copyW(0); copyX(0); CPA_COMMIT();
    for (int s = 0; s < 64; s++) {
        const int ch = s >> 2, tt = s & 3;
        if (s + 1 < 64) {
            if (tt == 3) copyW(ch + 1);
            copyX(s + 1);
            CPA_COMMIT();
            CPA_WAIT1();
        } else CPA_WAIT0();
        __syncthreads();
        const u32 wbuf = sb32 + (ch & 1) * 18432;
        const u32 xbuf = sb32 + 36864 + (s & 1) * 18432;
        const u32 abase = xbuf + (mt + row) * 144 + lh * 16;
        const u32 bbase = wbuf + row * 144 + (nh + lh * 8) * 2;
#pragma unroll
        for (int k16 = 0; k16 < 4; k16++)
            mma_k16(acc[tt], abase + k16 * 32, 9216, bbase + k16 * 2304, 9216);
        __syncthreads();
    }

    const int r0 = lane >> 2, c0 = (lane & 3) * 2;
#pragma unroll
    for (int tt = 0; tt < 4; tt++) {
        const int t = tg * 4 + tt;
#pragma unroll
        for (int na = 0; na < 4; na++) {
            int col = n0 + nh + na * 8 + c0;
            float2 bv = *reinterpret_cast<const float2*>(&bia[col]);
            *reinterpret_cast<float2*>(&outg[((size_t)t * Bb + mt + r0) * ldn + col]) =
                make_float2(acc[tt][na][0] + bv.x, acc[tt][na][1] + bv.y);
            *reinterpret_cast<float2*>(&outg[((size_t)t * Bb + mt + r0 + 8) * ldn + col]) =
                make_float2(acc[tt][na][2] + bv.x, acc[tt][na][3] + bv.y);
        }
    }
}

// ---------------- persistent recurrence: FULL-K, 2 barriers / step ----------------
// Phase A: block bx computes gate cols [bx*16, bx*16+16), all 64 b, K=1024.
//          h streamed hi/lo bf16 (cp.async.cg) in 8 double-buffered k128 chunks.
//          Tail: +Gx, sigmoid; bx<64 -> write rh hi/lo bf16; else write u fp32. BAR.
// Phase B: block bx computes cand cols [bx*8, bx*8+8), all 64 b, K=1024 with
//          intra-block k-split (warp pairs on even/odd chunks, smem reduce).
//          Tail (fused update): u(ldcg) + tanh + h update -> g_h, g_hhi/lo, out. BAR.
// Weights resident: wA 16 cols x 1024 k, 64B/row XOR-chunk swizzle (64KB);
//                   wB 8 cols x 1024 k, 32B/row XOR swizzle (32KB).
#define OFF_WA 0
#define OFF_WB 65536
#define OFF_HB 98304
#define HBUF   34816        // per buffer: hi 64x272 + lo 64x272
#define REC_SMEM 167936

__global__ void __launch_bounds__(256) gru_persist(float* __restrict__ out)
{
    extern __shared__ char smp[];
    const u32 sb32 = smem_u32(smp);
    const int tid = threadIdx.x, bx = blockIdx.x;
    const int lane = tid & 31, w = tid >> 5;
    const int row16 = lane & 15, lh = lane >> 4;
    const int r0 = lane >> 2, c0f = (lane & 3) * 2;
    const int mtA = (w & 3) * 16, nhA = w >> 2;  // phase A: 4 m-tiles x 2 n-halves
    const int mtB = (w & 3) * 16, khB = w >> 2;  // phase B: 4 m-tiles x 2 k-halves

    // ---- one-time: resident weight slices with XOR-chunk swizzle ----
    {
        const u32* wsh = (const u32*)g_Whi;
        const u32* wsl = (const u32*)g_Wlo;
        for (int i = tid; i < 1024 * 16; i += 256) {
            int r = i >> 4, w16 = i & 15;
            int g = w16 >> 2, c4 = w16 & 3;         // g: 0 hi-n0_7, 1 hi-n8_15, 2 lo-n0_7, 3 lo-n8_15
            int nOff = (g & 1) * 8 + c4 * 2;
            const u32* srcp = (g < 2) ? wsh : wsl;
            u32 v = srcp[(size_t)(Dd + r) * 1024 + bx * 8 + (nOff >> 1)];
            int cs = g ^ ((r >> 1) & 3);
            *(u32*)(smp + OFF_WA + r * 64 + cs * 16 + c4 * 4) = v;
        }
        const u32* ush = (const u32*)g_Uhi;
        const u32* usl = (const u32*)g_Ulo;
        for (int i = tid; i < 1024 * 8; i += 256) {
            int r = i >> 3, w8 = i & 7;
            int g = w8 >> 2, c4 = w8 & 3;           // g: 0 hi, 1 lo
            const u32* srcp = (g == 0) ? ush : usl;
            u32 v = srcp[(size_t)(Dd + r) * 512 + bx * 4 + c4];
            int cs = g ^ ((r >> 2) & 1);
            *(u32*)(smp + OFF_WB + r * 32 + cs * 16 + c4 * 4) = v;
        }
    }
    __syncthreads();

    const unsigned basec = ld_acq(&g_arrive);
    unsigned epoch = 0;

#define GRID_BAR()                                                           \
    do {                                                                     \
        __syncthreads();                                                     \
        epoch++;                                                             \
        if (tid == 0) {                                                      \
            red_release(&g_arrive);                                          \
            while ((unsigned)(ld_acq(&g_arrive) - basec) < epoch * Gblk) ;   \
        }                                                                    \
        __syncthreads();                                                     \
    } while (0)

    // cp.async stage one k128 chunk of a [64 x 1024] hi/lo bf16 pair.
    auto copyChunk = [&](int q, const __nv_bfloat16* hi, const __nv_bfloat16* lo) {
        const u32 buf = sb32 + OFF_HB + (q & 1) * HBUF;
#pragma unroll
        for (int j = 0; j < 8; j++) {
            int idx = j * 256 + tid;               // 0..2047
            bool isLo = idx >= 1024;
            int ii = idx & 1023;
            int r = ii >> 4, c = ii & 15;
            const __nv_bfloat16* src = (isLo ? lo : hi) + (size_t)r * 1024 + q * 128 + c * 8;
            CPA16(buf + (isLo ? 17408 : 0) + r * 272 + c * 16, src);
        }
        CPA_COMMIT();
    };

    for (int t = 0; t < Tt; ++t) {
        // prefetch the per-block Gx / Cx tail slices
        if (tid < 64)
            prefetch_l2(&g_Gx[(size_t)t * (Bb * 2048) + (size_t)tid * 2048 + bx * 16]);
        else if (tid < 128)
            prefetch_l2(&g_Cx[(size_t)t * (Bb * 1024) + (size_t)(tid - 64) * 1024 + bx * 8]);

        // ================= Phase A: gates (full K) =================
        {
            float acc[4] = {0.f, 0.f, 0.f, 0.f};
            copyChunk(0, g_hhi, g_hlo);
            for (int q = 0; q < 8; q++) {
                if (q + 1 < 8) { copyChunk(q + 1, g_hhi, g_hlo); CPA_WAIT1(); }
                else CPA_WAIT0();
                __syncthreads();
                const u32 buf = sb32 + OFF_HB + (q & 1) * HBUF;
                const u32 abase = buf + (mtA + row16) * 272 + lh * 16;
#pragma unroll
                for (int k16 = 0; k16 < 8; k16++) {
                    u32 ah[4], al[4];
                    ldm4(ah, abase + k16 * 32);
                    ldm4(al, abase + k16 * 32 + 17408);
                    int kr = q * 128 + k16 * 16 + row16;
                    int sw = (kr >> 1) & 3;
                    u32 bh0, bh1, bl0, bl1;
                    ldm2t(bh0, bh1, sb32 + OFF_WA + kr * 64 + ((nhA ^ sw) << 4));
                    ldm2t(bl0, bl1, sb32 + OFF_WA + kr * 64 + (((2 | nhA) ^ sw) << 4));
                    mmaA(acc, ah, bh0, bh1);
                    mmaA(acc, al, bh0, bh1);
                    mmaA(acc, ah, bl0, bl1);
                }
                __syncthreads();
            }
            // tail: +Gx, sigmoid; write rh (r-blocks) or u (u-blocks)
            const int colg = bx * 16 + nhA * 8 + c0f;
#pragma unroll
            for (int half = 0; half < 2; half++) {
                const int b = mtA + r0 + half * 8;
                float2 gx = *reinterpret_cast<const float2*>(
                    &g_Gx[(size_t)t * (Bb * 2048) + (size_t)b * 2048 + colg]);
                float g0 = sigf(acc[half * 2 + 0] + gx.x);
                float g1 = sigf(acc[half * 2 + 1] + gx.y);
                if (bx < 64) {
                    float2 h2 = __ldcg(reinterpret_cast<const float2*>(&g_h[b * 1024 + colg]));
                    float v0 = g0 * h2.x, v1 = g1 * h2.y;
                    __nv_bfloat16 b0 = bfh(v0), b1 = bfh(v1);
                    *reinterpret_cast<u32*>(&g_rhhi[b * 1024 + colg]) = pk(b0, b1);
                    *reinterpret_cast<u32*>(&g_rhlo[b * 1024 + colg]) =
                        pk(bfl(v0, b0), bfl(v1, b1));
                } else {
                    *reinterpret_cast<float2*>(&g_u[b * 1024 + colg - 1024]) =
                        make_float2(g0, g1);
                }
            }
        }
        GRID_BAR();

        // ========== Phase B: candidate (full K, intra-block k-split) + update ==========
        {
            float acc[4] = {0.f, 0.f, 0.f, 0.f};
            copyChunk(0, g_rhhi, g_rhlo);
            for (int q = 0; q < 8; q++) {
                if (q + 1 < 8) { copyChunk(q + 1, g_rhhi, g_rhlo); CPA_WAIT1(); }
                else CPA_WAIT0();
                __syncthreads();
                if ((q & 1) == khB) {
                    const u32 buf = sb32 + OFF_HB + (q & 1) * HBUF;
                    const u32 abase = buf + (mtB + row16) * 272 + lh * 16;
#pragma unroll
                    for (int k16 = 0; k16 < 8; k16++) {
                        u32 ah[4], al[4];
                        ldm4(ah, abase + k16 * 32);
                        ldm4(al, abase + k16 * 32 + 17408);
                        int kr = q * 128 + k16 * 16 + row16;
                        int sw = (kr >> 2) & 1;
                        u32 bh0, bh1, bl0, bl1;
                        ldm2t(bh0, bh1, sb32 + OFF_WB + kr * 32 + ((0 ^ sw) << 4));
                        ldm2t(bl0, bl1, sb32 + OFF_WB + kr * 32 + ((1 ^ sw) << 4));
                        mmaA(acc, ah, bh0, bh1);
                        mmaA(acc, al, bh0, bh1);
                        mmaA(acc, ah, bl0, bl1);
                    }
                }
                __syncthreads();
            }
            // intra-block k reduce (kh=1 warps publish; kh=0 warps consume)
            if (khB == 1)
                *reinterpret_cast<float4*>(smp + OFF_HB + (w - 4) * 512 + lane * 16) =
                    make_float4(acc[0], acc[1], acc[2], acc[3]);
            __syncthreads();
            if (khB == 0) {
                float4 o = *reinterpret_cast<const float4*>(smp + OFF_HB + w * 512 + lane * 16);
                acc[0] += o.x; acc[1] += o.y; acc[2] += o.z; acc[3] += o.w;
                // fused update tail
                const int colc = bx * 8 + c0f;
#pragma unroll
                for (int half = 0; half < 2; half++) {
                    const int b = mtB + r0 + half * 8;
                    float2 cx = *reinterpret_cast<const float2*>(
                        &g_Cx[(size_t)t * (Bb * 1024) + (size_t)b * 1024 + colc]);
                    float2 uu = __ldcg(reinterpret_cast<const float2*>(&g_u[b * 1024 + colc]));
                    float2 h2 = *reinterpret_cast<const float2*>(&g_h[b * 1024 + colc]);
                    float c0v = tanh_fast(acc[half * 2 + 0] + cx.x);
                    float c1v = tanh_fast(acc[half * 2 + 1] + cx.y);
                    float2 hn;
                    hn.x = uu.x * h2.x + (1.0f - uu.x) * c0v;
                    hn.y = uu.y * h2.y + (1.0f - uu.y) * c1v;
                    *reinterpret_cast<float2*>(&g_h[b * 1024 + colc]) = hn;
                    __nv_bfloat16 b0 = bfh(hn.x), b1 = bfh(hn.y);
                    *reinterpret_cast<u32*>(&g_hhi[b * 1024 + colc]) = pk(b0, b1);
                    *reinterpret_cast<u32*>(&g_hlo[b * 1024 + colc]) =
                        pk(bfl(hn.x, b0), bfl(hn.y, b1));
                    *reinterpret_cast<float2*>(&out[((size_t)b * Tt + t) * 1024 + colc]) = hn;
                }
            }
        }
        GRID_BAR();
    }
#undef GRID_BAR
}

extern "C" void kernel_launch(void* const* d_in, const int* in_sizes, int n_in,
                              void* d_out, int out_size)
{
    const float* x  = (const float*)d_in[0];
    const float* h0 = (const float*)d_in[1];
    const float* W  = (const float*)d_in[2];
    const float* Wb = (const float*)d_in[3];
    const float* U  = (const float*)d_in[4];
    const float* Ub = (const float*)d_in[5];
    float* out = (float*)d_out;

    cudaFuncSetAttribute(gemm_pre_tc, cudaFuncAttributeMaxDynamicSharedMemorySize, PRE_SMEM);
    cudaFuncSetAttribute(gru_persist, cudaFuncAttributeMaxDynamicSharedMemorySize, REC_SMEM);

    // one-time fp32 -> bf16 hi/lo splits
    conv_split<<<(Bb * Tt * Dd / 4 + 255) / 256, 256>>>((const float4*)x, 0, Bb * Tt * Dd / 4);
    conv_split<<<(2048 * 2048 / 4 + 255) / 256, 256>>>((const float4*)W, 1, 2048 * 2048 / 4);
    conv_split<<<(2048 * 1024 / 4 + 255) / 256, 256>>>((const float4*)U, 2, 2048 * 1024 / 4);

    copy_h0<<<Bb * Hh / 512, 256>>>(h0);

    // x-path precompute: Gx[t][b][n], Cx[t][b][n]  (t-batched x4)
    gemm_pre_tc<<<dim3(48, 128), 256, PRE_SMEM>>>(Wb, Ub);

    // persistent recurrence (2 barriers/step, no partial arrays)
    gru_persist<<<Gblk, 256, REC_SMEM>>>(out);
}

// round 17
// speedup vs baseline: 1.4154x; 1.4154x over previous
#include <cuda_runtime.h>
#include <cuda_bf16.h>

typedef unsigned int u32;
typedef unsigned long long u64;

#define Bb 64
#define Tt 512
#define Dd 1024
#define Hh 1024
#define Gblk 128

// ---------------- global scratch (allocation-free rule) ----------------
__device__ float g_Gx[(size_t)Tt * Bb * 2048];   // [t][b][n]
__device__ float g_Cx[(size_t)Tt * Bb * 1024];   // [t][b][n]
__device__ float g_h [Bb * Hh];                  // [b][c] fp32
__device__ float g_rh[Bb * Hh];
__device__ float g_u [Bb * Hh];
__device__ float g_pA[(size_t)8  * Bb * 2048];   // [ksplit][b][n]
__device__ float g_pB[(size_t)16 * Bb * 1024];
__device__ __nv_bfloat16 g_xhi[(size_t)Bb * Tt * Dd];
__device__ __nv_bfloat16 g_xlo[(size_t)Bb * Tt * Dd];
__device__ __nv_bfloat16 g_Whi[2048 * 2048];
__device__ __nv_bfloat16 g_Wlo[2048 * 2048];
__device__ __nv_bfloat16 g_Uhi[2048 * 1024];
__device__ __nv_bfloat16 g_Ulo[2048 * 1024];
__device__ unsigned g_arrive;                    // monotonic barrier counter

// ---------------- helpers ----------------
__device__ __forceinline__ unsigned ld_acq(const unsigned* p) {
    unsigned v; asm volatile("ld.global.acquire.gpu.u32 %0, [%1];" : "=r"(v) : "l"(p)); return v;
}
__device__ __forceinline__ void red_release(unsigned* p) {
    asm volatile("red.release.gpu.global.add.u32 [%0], 1;" :: "l"(p) : "memory");
}
__device__ __forceinline__ float sigf(float x) { return __fdividef(1.0f, 1.0f + __expf(-x)); }
__device__ __forceinline__ float tanh_fast(float x) {
    float e = __expf(-2.0f * x);
    return __fdividef(1.0f - e, 1.0f + e);
}
__device__ __forceinline__ u32 smem_u32(const void* p) {
    u32 a; asm("{ .reg .u64 t; cvta.to.shared.u64 t, %1; cvt.u32.u64 %0, t; }" : "=r"(a) : "l"(p));
    return a;
}
__device__ __forceinline__ u32 pk(__nv_bfloat16 a, __nv_bfloat16 b) {
    __nv_bfloat162 t; t.x = a; t.y = b; return *reinterpret_cast<u32*>(&t);
}
__device__ __forceinline__ __nv_bfloat16 bfh(float x) { return __float2bfloat16_rn(x); }
__device__ __forceinline__ __nv_bfloat16 bfl(float x, __nv_bfloat16 h) {
    return __float2bfloat16_rn(x - __bfloat162float(h));
}
__device__ __forceinline__ void prefetch_l2(const void* p) {
    asm volatile("prefetch.global.L2 [%0];" :: "l"(p));
}

// ---------------- tensor-core primitives (baseline PTX, sm_80+) ----------------
__device__ __forceinline__ void ldm4(u32* r, u32 a) {
    asm volatile("ldmatrix.sync.aligned.m8n8.x4.shared.b16 {%0,%1,%2,%3}, [%4];"
        : "=r"(r[0]), "=r"(r[1]), "=r"(r[2]), "=r"(r[3]) : "r"(a));
}
__device__ __forceinline__ void ldm4t(u32* r, u32 a) {
    asm volatile("ldmatrix.sync.aligned.m8n8.x4.trans.shared.b16 {%0,%1,%2,%3}, [%4];"
        : "=r"(r[0]), "=r"(r[1]), "=r"(r[2]), "=r"(r[3]) : "r"(a));
}
__device__ __forceinline__ void mmaA(float* d, const u32* a, u32 b0, u32 b1) {
    asm volatile("mma.sync.aligned.m16n8k16.row.col.f32.bf16.bf16.f32 "
        "{%0,%1,%2,%3}, {%4,%5,%6,%7}, {%8,%9}, {%0,%1,%2,%3};"
        : "+f"(d[0]), "+f"(d[1]), "+f"(d[2]), "+f"(d[3])
        : "r"(a[0]), "r"(a[1]), "r"(a[2]), "r"(a[3]), "r"(b0), "r"(b1));
}
#define CPA16(dst, src) \
    asm volatile("cp.async.cg.shared.global [%0], [%1], 16;" :: "r"(dst), "l"(src))
#define CPA_COMMIT() asm volatile("cp.async.commit_group;")
#define CPA_WAIT1()  asm volatile("cp.async.wait_group 1;")
#define CPA_WAIT0()  asm volatile("cp.async.wait_group 0;")

// One k16 step for a warp tile m16 x n32: 3-term bf16 split => 12 HMMA.
__device__ __forceinline__ void mma_k16(float (&acc)[4][4], u32 aaddr, u32 alo_d,
                                        u32 baddr, u32 blo_d) {
    u32 ah[4], al[4];
    ldm4(ah, aaddr);
    ldm4(al, aaddr + alo_d);
#pragma unroll
    for (int p = 0; p < 2; p++) {
        u32 bh[4], bl[4];
        ldm4t(bh, baddr + p * 32);
        ldm4t(bl, baddr + p * 32 + blo_d);
        mmaA(acc[2 * p],     ah, bh[0], bh[1]);
        mmaA(acc[2 * p],     al, bh[0], bh[1]);
        mmaA(acc[2 * p],     ah, bl[0], bl[1]);
        mmaA(acc[2 * p + 1], ah, bh[2], bh[3]);
        mmaA(acc[2 * p + 1], al, bh[2], bh[3]);
        mmaA(acc[2 * p + 1], ah, bl[2], bl[3]);
    }
}

// ---------------- conversion kernels ----------------
__global__ void __launch_bounds__(256) conv_split(
    const float4* __restrict__ src, int which, int n4)
{
    int i = blockIdx.x * blockDim.x + threadIdx.x;
    if (i >= n4) return;
    u32* hi; u32* lo;
    if (which == 0)      { hi = (u32*)g_xhi; lo = (u32*)g_xlo; }
    else if (which == 1) { hi = (u32*)g_Whi; lo = (u32*)g_Wlo; }
    else                 { hi = (u32*)g_Uhi; lo = (u32*)g_Ulo; }
    float4 v = src[i];
    __nv_bfloat16 hx = bfh(v.x), hy = bfh(v.y), hz = bfh(v.z), hw = bfh(v.w);
    hi[2 * i]     = pk(hx, hy);
    hi[2 * i + 1] = pk(hz, hw);
    lo[2 * i]     = pk(bfl(v.x, hx), bfl(v.y, hy));
    lo[2 * i + 1] = pk(bfl(v.z, hz), bfl(v.w, hw));
}

__global__ void __launch_bounds__(256) copy_h0(const float* __restrict__ h0)
{
    int i = blockIdx.x * blockDim.x + threadIdx.x;
    if (i < Bb * Hh) g_h[i] = h0[i];
}

// ---------------- precompute (x-path), t-batched (R13, unchanged) ----------------
#define PRE_SMEM 73728

__global__ void __launch_bounds__(256) gemm_pre_tc(
    const float* __restrict__ Wb, const float* __restrict__ Ub)
{
    extern __shared__ char smp[];
    const u32 sb32 = smem_u32(smp);
    const int tid = threadIdx.x;
    const int cb = blockIdx.x, tg = blockIdx.y;
    const bool isW = cb < 32;
    const __nv_bfloat16* whi = isW ? g_Whi : g_Uhi;
    const __nv_bfloat16* wlo = isW ? g_Wlo : g_Ulo;
    const float* bia = isW ? Wb : Ub;
    float* outg = isW ? g_Gx : g_Cx;
    const int ldn = isW ? 2048 : 1024;
    const int n0  = (isW ? cb : cb - 32) * 64;

    const int lane = tid & 31, w = tid >> 5;
    const int mt = (w & 3) * 16, nh = (w >> 2) * 32;
    const int row = lane & 15, lh = lane >> 4;

    float acc[4][4][4];
#pragma unroll
    for (int tt = 0; tt < 4; tt++)
#pragma unroll
        for (int i = 0; i < 4; i++)
#pragma unroll
            for (int j = 0; j < 4; j++) acc[tt][i][j] = 0.0f;

    auto copyW = [&](int ch) {
        const int k0 = ch * 64;
        const u32 wbuf = sb32 + (ch & 1) * 18432;
#pragma unroll
        for (int j = 0; j < 4; j++) {
            int idx = j * 256 + tid;
            int r = (idx >> 3) & 63, c8 = idx & 7;
            bool isLo = idx >= 512;
            const __nv_bfloat16* src = (isLo ? wlo : whi) + (size_t)(k0 + r) * ldn + n0 + c8 * 8;
            CPA16(wbuf + (isLo ? 9216 : 0) + r * 144 + c8 * 16, src);
        }
    };
    auto copyX = [&](int s) {
        const int ch = s >> 2, t = tg * 4 + (s & 3);
        const int k0 = ch * 64;
        const u32 xbuf = sb32 + 36864 + (s & 1) * 18432;
#pragma unroll
        for (int j = 0; j < 4; j++) {
            int idx = j * 256 + tid;
            int r = (idx >> 3) & 63, c8 = idx & 7;
            bool isLo = idx >= 512;
            const __nv_bfloat16* src = (isLo ? g_xlo : g_xhi) + ((size_t)r * Tt + t) * Dd + k0 + c8 * 8;
            CPA16(xbuf + (isLo ? 9216 : 0) + r * 144 + c8 * 16, src);
        }
    };

    copyW(0); copyX(0); CPA_COMMIT();
    for (int s = 0; s < 64; s++) {
        const int ch = s >> 2, tt = s & 3;
        if (s + 1 < 64) {
            if (tt == 3) copyW(ch + 1);
            copyX(s + 1);
            CPA_COMMIT();
            CPA_WAIT1();
        } else CPA_WAIT0();
        __syncthreads();
        const u32 wbuf = sb32 + (ch & 1) * 18432;
        const u32 xbuf = sb32 + 36864 + (s & 1) * 18432;
        const u32 abase = xbuf + (mt + row) * 144 + lh * 16;
        const u32 bbase = wbuf + row * 144 + (nh + lh * 8) * 2;
#pragma unroll
        for (int k16 = 0; k16 < 4; k16++)
            mma_k16(acc[tt], abase + k16 * 32, 9216, bbase + k16 * 2304, 9216);
        __syncthreads();
    }

    const int r0 = lane >> 2, c0 = (lane & 3) * 2;
#pragma unroll
    for (int tt = 0; tt < 4; tt++) {
        const int t = tg * 4 + tt;
#pragma unroll
        for (int na = 0; na < 4; na++) {
            int col = n0 + nh + na * 8 + c0;
            float2 bv = *reinterpret_cast<const float2*>(&bia[col]);
            *reinterpret_cast<float2*>(&outg[((size_t)t * Bb + mt + r0) * ldn + col]) =
                make_float2(acc[tt][na][0] + bv.x, acc[tt][na][1] + bv.y);
            *reinterpret_cast<float2*>(&outg[((size_t)t * Bb + mt + r0 + 8) * ldn + col]) =
                make_float2(acc[tt][na][2] + bv.x, acc[tt][na][3] + bv.y);
        }
    }
}

// ---------------- persistent recurrence: 128 CTAs x 512 threads ----------------
// Each CTA hosts TWO virtual blocks (vbx = 2*bx + (tid>>8)), each with its own
// 90KB smem region -> 16 warps/SM of latency hiding with GUARANTEED residency.
// Phase A: vb: 32 colblocks(64 n of 2048) x 8 ksplits(K=128) -> pA.  BAR.
// A-reduce: sum 8 partials + Gx, sigmoid -> rh / u.                  BAR.
// Phase B: vb: 16 colblocks(64 n of 1024) x 16 ksplits(K=64) -> pB.  BAR.
// Update : sum 16 partials + Cx, tanh, h update -> g_h, out.         BAR.
#define OFF_WAHI 0
#define OFF_WALO 18432
#define OFF_WBHI 36864
#define OFF_WBLO 46080
#define OFF_HHI  55296
#define OFF_HLO  72704      // HHI + 64*272
#define VREG     90112      // per-virtual-block smem region
#define REC_SMEM (2 * VREG) // 180224

__global__ void __launch_bounds__(512, 1) gru_persist(float* __restrict__ out)
{
    extern __shared__ char smp[];
    const int tid  = threadIdx.x;
    const int half = tid >> 8;            // which virtual block
    const int ltid = tid & 255;
    const int vbx  = blockIdx.x * 2 + half;
    char* bm = smp + half * VREG;
    const u32 base32 = smem_u32(smp) + half * VREG;

    const int lane = ltid & 31, w = ltid >> 5;
    const int mt = (w & 3) * 16, nh = (w >> 2) * 32;
    const int row = lane & 15, lh = lane >> 4;
    const int r0 = lane >> 2, c0 = (lane & 3) * 2;
    const int ca = vbx & 31, sa = vbx >> 5;   // phase A: 32 cb x 8 ks
    const int cbp = vbx & 15, sbp = vbx >> 4; // phase B: 16 cb x 16 ks

    // ---- one-time: load resident weight slices (per virtual block) ----
    {
        const u32* wsh = reinterpret_cast<const u32*>(g_Whi);
        const u32* wsl = reinterpret_cast<const u32*>(g_Wlo);
        for (int i = ltid; i < 128 * 32; i += 256) {
            int r = i >> 5, c = i & 31;
            size_t s = ((size_t)(Dd + sa * 128 + r) * 2048 + ca * 64) / 2 + c;
            *reinterpret_cast<u32*>(bm + OFF_WAHI + r * 144 + c * 4) = wsh[s];
            *reinterpret_cast<u32*>(bm + OFF_WALO + r * 144 + c * 4) = wsl[s];
        }
        const u32* ush = reinterpret_cast<const u32*>(g_Uhi);
        const u32* usl = reinterpret_cast<const u32*>(g_Ulo);
        for (int i = ltid; i < 64 * 32; i += 256) {
            int r = i >> 5, c = i & 31;
            size_t s = ((size_t)(Dd + sbp * 64 + r) * 1024 + cbp * 64) / 2 + c;
            *reinterpret_cast<u32*>(bm + OFF_WBHI + r * 144 + c * 4) = ush[s];
            *reinterpret_cast<u32*>(bm + OFF_WBLO + r * 144 + c * 4) = usl[s];
        }
    }
    __syncthreads();

    const unsigned basec = ld_acq(&g_arrive);
    unsigned epoch = 0;

#define GRID_BAR()                                                           \
    do {                                                                     \
        __syncthreads();                                                     \
        epoch++;                                                             \
        if (tid == 0) {                                                      \
            red_release(&g_arrive);                                          \
            while ((unsigned)(ld_acq(&g_arrive) - basec) < epoch * Gblk) ;   \
        }                                                                    \
        __syncthreads();                                                     \
    } while (0)

    // Coalesced fp32 -> bf16 hi/lo staging, row stride 272 (fits K<=128).
    auto stage_h = [&](const float* src, int kbase, int lg) {
        const int iters = (lg == 5) ? 8 : 4;
        const int mask = (1 << lg) - 1;
        for (int j = 0; j < iters; j++) {
            int idx = j * 256 + ltid;
            int r = idx >> lg, c4 = idx & mask;
            float4 a = *reinterpret_cast<const float4*>(src + (size_t)r * 1024 + kbase + c4 * 4);
            __nv_bfloat16 h0 = bfh(a.x), h1 = bfh(a.y), h2 = bfh(a.z), h3 = bfh(a.w);
            *reinterpret_cast<uint2*>(bm + OFF_HHI + r * 272 + c4 * 8) =
                make_uint2(pk(h0, h1), pk(h2, h3));
            *reinterpret_cast<uint2*>(bm + OFF_HLO + r * 272 + c4 * 8) =
                make_uint2(pk(bfl(a.x, h0), bfl(a.y, h1)), pk(bfl(a.z, h2), bfl(a.w, h3)));
        }
    };

    const u32 abase0 = base32 + OFF_HHI + (mt + row) * 272 + lh * 16;
    const u32 baseA  = base32 + OFF_WAHI + row * 144 + (nh + lh * 8) * 2;
    const u32 baseB  = base32 + OFF_WBHI + row * 144 + (nh + lh * 8) * 2;

    for (int t = 0; t < Tt; ++t) {
        // L2 prefetch for the reduce phases (this virtual block's slices)
        if (ltid < 16)
            prefetch_l2(&g_Gx[(size_t)t * (Bb * 2048) + vbx * 512 + ltid * 32]);
        else if (ltid < 24)
            prefetch_l2(&g_Cx[(size_t)t * (Bb * 1024) + vbx * 256 + (ltid - 16) * 32]);

        // ---------------- Phase A: gate partials (K=128) ----------------
        {
            stage_h(g_h, sa * 128, 5);
            __syncthreads();
            float acc[4][4];
#pragma unroll
            for (int i = 0; i < 4; i++)
#pragma unroll
                for (int j = 0; j < 4; j++) acc[i][j] = 0.0f;
#pragma unroll
            for (int k16 = 0; k16 < 8; k16++)
                mma_k16(acc, abase0 + k16 * 32, OFF_HLO - OFF_HHI,
                        baseA + k16 * 2304, OFF_WALO - OFF_WAHI);
            float* pa = g_pA + (size_t)sa * (Bb * 2048);
#pragma unroll
            for (int na = 0; na < 4; na++) {
                int col = ca * 64 + nh + na * 8 + c0;
                *reinterpret_cast<float2*>(&pa[(size_t)(mt + r0) * 2048 + col]) =
                    make_float2(acc[na][0], acc[na][1]);
                *reinterpret_cast<float2*>(&pa[(size_t)(mt + r0 + 8) * 2048 + col]) =
                    make_float2(acc[na][2], acc[na][3]);
            }
        }
        GRID_BAR();

        // ---------------- A-reduce: sigmoid gates ----------------
        {
            const int flat = vbx * 512 + ltid * 2;  // = b*2048 + n
            const int b = flat >> 11, n = flat & 2047;
            float2 a = *reinterpret_cast<const float2*>(&g_Gx[(size_t)t * (Bb * 2048) + flat]);
#pragma unroll
            for (int s = 0; s < 8; s++) {
                float2 p = *reinterpret_cast<const float2*>(&g_pA[(size_t)s * (Bb * 2048) + flat]);
                a.x += p.x; a.y += p.y;
            }
            float2 g = make_float2(sigf(a.x), sigf(a.y));
            if (n < 1024) {
                float2 h2 = *reinterpret_cast<const float2*>(&g_h[b * 1024 + n]);
                *reinterpret_cast<float2*>(&g_rh[b * 1024 + n]) =
                    make_float2(g.x * h2.x, g.y * h2.y);
            } else {
                *reinterpret_cast<float2*>(&g_u[b * 1024 + (n - 1024)]) = g;
            }
        }
        GRID_BAR();

        // ---------------- Phase B: candidate partials (K=64) ----------------
        {
            stage_h(g_rh, sbp * 64, 4);
            __syncthreads();
            float acc[4][4];
#pragma unroll
            for (int i = 0; i < 4; i++)
#pragma unroll
                for (int j = 0; j < 4; j++) acc[i][j] = 0.0f;
#pragma unroll
            for (int k16 = 0; k16 < 4; k16++)
                mma_k16(acc, abase0 + k16 * 32, OFF_HLO - OFF_HHI,
                        baseB + k16 * 2304, OFF_WBLO - OFF_WBHI);
            float* pb = g_pB + (size_t)sbp * (Bb * 1024);
#pragma unroll
            for (int na = 0; na < 4; na++) {
                int col = cbp * 64 + nh + na * 8 + c0;
                *reinterpret_cast<float2*>(&pb[(size_t)(mt + r0) * 1024 + col]) =
                    make_float2(acc[na][0], acc[na][1]);
                *reinterpret_cast<float2*>(&pb[(size_t)(mt + r0 + 8) * 1024 + col]) =
                    make_float2(acc[na][2], acc[na][3]);
            }
        }
        GRID_BAR();

        // ---------------- Update: tanh + state update ----------------
        {
            const int flat = vbx * 256 + ltid;      // = b*1024 + n (scalar)
            const int b = flat >> 10, n = flat & 1023;
            float a = g_Cx[(size_t)t * (Bb * 1024) + flat];
#pragma unroll
            for (int s = 0; s < 16; s++)
                a += g_pB[(size_t)s * (Bb * 1024) + flat];
            float uu = g_u[flat];
            float hh = g_h[flat];
            float hn = uu * hh + (1.0f - uu) * tanh_fast(a);
            g_h[flat] = hn;
            out[((size_t)b * Tt + t) * 1024 + n] = hn;
        }
        GRID_BAR();
    }
#undef GRID_BAR
}

extern "C" void kernel_launch(void* const* d_in, const int* in_sizes, int n_in,
                              void* d_out, int out_size)
{
    const float* x  = (const float*)d_in[0];
    const float* h0 = (const float*)d_in[1];
    const float* W  = (const float*)d_in[2];
    const float* Wb = (const float*)d_in[3];
    const float* U  = (const float*)d_in[4];
    const float* Ub = (const float*)d_in[5];
    float* out = (float*)d_out;

    cudaFuncSetAttribute(gemm_pre_tc, cudaFuncAttributeMaxDynamicSharedMemorySize, PRE_SMEM);
    cudaFuncSetAttribute(gru_persist, cudaFuncAttributeMaxDynamicSharedMemorySize, REC_SMEM);

    // one-time fp32 -> bf16 hi/lo splits
    conv_split<<<(Bb * Tt * Dd / 4 + 255) / 256, 256>>>((const float4*)x, 0, Bb * Tt * Dd / 4);
    conv_split<<<(2048 * 2048 / 4 + 255) / 256, 256>>>((const float4*)W, 1, 2048 * 2048 / 4);
    conv_split<<<(2048 * 1024 / 4 + 255) / 256, 256>>>((const float4*)U, 2, 2048 * 1024 / 4);

    copy_h0<<<(Bb * Hh) / 256, 256>>>(h0);

    // x-path precompute: Gx[t][b][n], Cx[t][b][n]  (t-batched x4)
    gemm_pre_tc<<<dim3(48, 128), 256, PRE_SMEM>>>(Wb, Ub);

    // persistent recurrence: 128 CTAs x 512 threads (2 virtual blocks/CTA)
    gru_persist<<<Gblk, 512, REC_SMEM>>>(out);
}